// round 14
// baseline (speedup 1.0000x reference)
#include <cuda_runtime.h>
#include <cuda_fp16.h>
#include <mma.h>
#include <cstdint>
using namespace nvcuda;

// Problem constants
#define B     4
#define N     8192
#define CIN   256
#define H     8
#define D     64
#define INNER 512
#define COUT  256
#define BH    (B*H)
#define KEXT  512          // hi(256) | lo(256)
#define LDH   72           // smem fp16 ld (conflict-free LDSM)
#define LDC   132          // smem fp32 C ld
#define TG1   8            // row-tiles per k1w block
#define TG4   4            // row-tiles per k4w block
#define NG1   16           // k1w tile-groups

// k1w smem layout (bytes): sA/kHI [0,9216) ; sW/kLO+vH [9216,27648) ; sC [27648,61440) ; stat [61440,62464)
#define K1_W    9216
#define K1_KLO  9216
#define K1_VH   18432
#define K1_C    27648
#define K1_STAT 61440
#define SMEM_K1 62464
// k4w: sA [0,9216) ; sW [9216,27648) ; sC aliases [0,33792)
#define SMEM_K4 33792

// ---- device scratch ----
__device__ __align__(16) __half g_ah[(size_t)B * N * KEXT];      // 32 MB A ext (hi|lo)
__device__ __align__(16) __half g_wkv16[H * 128 * CIN];          // per-head [Wk|Wv] fp16
__device__ __align__(16) __half g_wf16[B * COUT * CIN];          // folded weight fp16
__device__ float g_part[(size_t)BH * NG1 * D * D];               // 8 MB dots partials
__device__ float g_dots[BH * D * D];
__device__ float g_wqe[B * INNER * CIN];
__device__ float g_wfin[B * COUT * CIN];

__device__ __forceinline__ uint32_t packh2(float a, float b) {
    __half2 h = __floats2half2_rn(a, b);
    return *reinterpret_cast<uint32_t*>(&h);
}

// ============ k0a: build A ext (hi|lo fp16) ============
__global__ __launch_bounds__(256) void k0a(const float* __restrict__ ux) {
    size_t i0 = (size_t)blockIdx.x * 256 + threadIdx.x;
    const float4* src = (const float4*)ux;
    for (size_t i = i0; i < (size_t)B * N * 64; i += 65536) {
        size_t row = i >> 6;
        int c4 = (int)(i & 63);
        float4 f = src[i];
        __half h0 = __float2half_rn(f.x), h1 = __float2half_rn(f.y);
        __half h2 = __float2half_rn(f.z), h3 = __float2half_rn(f.w);
        uint2 hi, lo;
        hi.x = (uint32_t)__half_as_ushort(h0) | ((uint32_t)__half_as_ushort(h1) << 16);
        hi.y = (uint32_t)__half_as_ushort(h2) | ((uint32_t)__half_as_ushort(h3) << 16);
        lo.x = packh2(f.x - __half2float(h0), f.y - __half2float(h1));
        lo.y = packh2(f.z - __half2float(h2), f.w - __half2float(h3));
        __half* dst = g_ah + row * KEXT + c4 * 4;
        *(uint2*)dst = hi;
        *(uint2*)(dst + CIN) = lo;
    }
}
// ============ k0w: [Wk|Wv] head images fp16 ============
__global__ __launch_bounds__(256) void k0w(const float* __restrict__ Wk,
                                           const float* __restrict__ Wv) {
    int h = blockIdx.x, tid = threadIdx.x;
    for (int i = tid; i < 8192; i += 256) {
        int r = i >> 6, c = (i & 63) * 4;
        const float* src = (r < 64) ? (Wk + ((size_t)(h * 64 + r)) * CIN + c)
                                    : (Wv + ((size_t)(h * 64 + r - 64)) * CIN + c);
        float4 f = *(const float4*)src;
        uint2 v;
        v.x = packh2(f.x, f.y);
        v.y = packh2(f.z, f.w);
        *(uint2*)(g_wkv16 + (size_t)h * 32768 + r * CIN + c) = v;
    }
}
// ============ K1: wmma proj + shfl norm + wmma dots ============
__global__ __launch_bounds__(256, 3) void k1w() {
    const int g = blockIdx.x, h = blockIdx.y, b = blockIdx.z;
    const int bh = b * H + h;
    const int tid = threadIdx.x, wid = tid >> 5;
    const int wr = wid >> 1, wc = wid & 1;

    extern __shared__ __align__(16) char sm[];
    __half* sA  = (__half*)sm;                   // [64][72]  (mainloop)
    __half* sW  = (__half*)(sm + K1_W);          // [128][72] (mainloop)
    __half* kHI = (__half*)sm;                   // [64][72]  (epilogue, aliases sA)
    __half* kLO = (__half*)(sm + K1_KLO);        // [64][72]  (aliases sW lo half)
    __half* vH  = (__half*)(sm + K1_VH);         // [64][72]
    float*  sC  = (float*)(sm + K1_C);           // [64][132]
    float*  sStat = (float*)(sm + K1_STAT);      // mean[128] rstd[128]

    // dots accumulators live across all 8 tiles
    wmma::fragment<wmma::accumulator, 16, 16, 16, float> dc0, dc1;
    wmma::fill_fragment(dc0, 0.0f);
    wmma::fill_fragment(dc1, 0.0f);
    const int d0 = (wid >> 1) * 16, e0 = (wid & 1) * 32;

    const __half* wsrc = g_wkv16 + (size_t)h * 32768;

    for (int t = 0; t < TG1; ++t) {
        const int row0 = (g * TG1 + t) * 64;
        const __half* abase = g_ah + ((size_t)(b * N + row0)) * KEXT;

        wmma::fragment<wmma::accumulator, 16, 16, 16, float> c[4];
#pragma unroll
        for (int f = 0; f < 4; ++f) wmma::fill_fragment(c[f], 0.0f);

        for (int kt = 0; kt < KEXT; kt += 64) {
            int ktw = kt & (CIN - 1);
            __syncthreads();
#pragma unroll
            for (int l = 0; l < 2; ++l) {            // A 64x64
                int idx = tid + l * 256;
                int r = idx >> 3, c8 = (idx & 7) * 8;
                *(uint4*)(sA + r * LDH + c8) = *(const uint4*)(abase + (size_t)r * KEXT + kt + c8);
            }
#pragma unroll
            for (int l = 0; l < 4; ++l) {            // W 128x64
                int idx = tid + l * 256;
                int r = idx >> 3, c8 = (idx & 7) * 8;
                *(uint4*)(sW + r * LDH + c8) = *(const uint4*)(wsrc + (size_t)r * CIN + ktw + c8);
            }
            __syncthreads();
#pragma unroll
            for (int ks = 0; ks < 4; ++ks) {
                wmma::fragment<wmma::matrix_a, 16, 16, 16, __half, wmma::row_major> a;
                wmma::load_matrix_sync(a, sA + (wr * 16) * LDH + ks * 16, LDH);
#pragma unroll
                for (int cf = 0; cf < 4; ++cf) {
                    wmma::fragment<wmma::matrix_b, 16, 16, 16, __half, wmma::col_major> bf;
                    wmma::load_matrix_sync(bf, sW + (wc * 64 + cf * 16) * LDH + ks * 16, LDH);
                    wmma::mma_sync(c[cf], a, bf, c[cf]);
                }
            }
        }
        __syncthreads();
#pragma unroll
        for (int cf = 0; cf < 4; ++cf)
            wmma::store_matrix_sync(sC + (wr * 16) * LDC + wc * 64 + cf * 16, c[cf],
                                    LDC, wmma::mem_row_major);
        __syncthreads();

        // stats: 2 threads per (row,grp), shfl-combine
        {
            int p = tid >> 1, h2 = tid & 1;
            int row = p & 63, grp = p >> 6;
            const float* pr = sC + row * LDC + grp * 64 + h2 * 32;
            float s = 0.f, s2 = 0.f;
#pragma unroll
            for (int i = 0; i < 32; ++i) { float x = pr[i]; s += x; s2 += x * x; }
            s  += __shfl_xor_sync(0xFFFFFFFF, s, 1);
            s2 += __shfl_xor_sync(0xFFFFFFFF, s2, 1);
            if (h2 == 0) {
                float mean = s * (1.f / 64.f);
                float var = s2 * (1.f / 64.f) - mean * mean;
                sStat[grp * 64 + row] = mean;
                sStat[128 + grp * 64 + row] = rsqrtf(var + 1e-5f);
            }
        }
        __syncthreads();

        // normalize -> fp16 operands (natural [n][.] layout; k gets hi/lo split)
        {
            int part = tid >> 6, n = tid & 63;
            if (part < 2) {
                float m = sStat[n], rs = sStat[128 + n];
                int c0 = part * 32;
                const float* src = sC + n * LDC + c0;
#pragma unroll
                for (int j = 0; j < 16; ++j) {
                    float x0 = (src[2 * j] - m) * rs;
                    float x1 = (src[2 * j + 1] - m) * rs;
                    __half h0 = __float2half_rn(x0), h1 = __float2half_rn(x1);
                    uint32_t hi = (uint32_t)__half_as_ushort(h0) | ((uint32_t)__half_as_ushort(h1) << 16);
                    uint32_t lo = packh2(x0 - __half2float(h0), x1 - __half2float(h1));
                    *(uint32_t*)(kHI + n * LDH + c0 + 2 * j) = hi;
                    *(uint32_t*)(kLO + n * LDH + c0 + 2 * j) = lo;
                }
            } else {
                float m = sStat[64 + n], rs = sStat[192 + n];
                int c0 = (part - 2) * 32;
                const float* src = sC + n * LDC + 64 + c0;
#pragma unroll
                for (int j = 0; j < 16; ++j) {
                    float x0 = (src[2 * j] - m) * rs;
                    float x1 = (src[2 * j + 1] - m) * rs;
                    *(uint32_t*)(vH + n * LDH + c0 + 2 * j) = packh2(x0, x1);
                }
            }
        }
        __syncthreads();

        // dots via wmma: dots[d,e] += sum_n khat[n,d]*vhat[n,e]
#pragma unroll
        for (int ns = 0; ns < 4; ++ns) {
            wmma::fragment<wmma::matrix_b, 16, 16, 16, __half, wmma::row_major> b0, b1;
            wmma::load_matrix_sync(b0, vH + ns * 16 * LDH + e0, LDH);
            wmma::load_matrix_sync(b1, vH + ns * 16 * LDH + e0 + 16, LDH);
            wmma::fragment<wmma::matrix_a, 16, 16, 16, __half, wmma::col_major> ah, al;
            wmma::load_matrix_sync(ah, kHI + d0 + ns * 16 * LDH, LDH);
            wmma::mma_sync(dc0, ah, b0, dc0);
            wmma::mma_sync(dc1, ah, b1, dc1);
            wmma::load_matrix_sync(al, kLO + d0 + ns * 16 * LDH, LDH);
            wmma::mma_sync(dc0, al, b0, dc0);
            wmma::mma_sync(dc1, al, b1, dc1);
        }
        // next tile's first barrier protects kHI/kLO/vH (alias sA/sW) and sC
    }

    float* pp = g_part + ((size_t)(bh * NG1 + g)) * 4096;
    wmma::store_matrix_sync(pp + d0 * 64 + e0, dc0, 64, wmma::mem_row_major);
    wmma::store_matrix_sync(pp + d0 * 64 + e0 + 16, dc1, 64, wmma::mem_row_major);
}
// ============ k2: reduce 16 partials ============
__global__ __launch_bounds__(256) void k2_reduce() {
    int gid = blockIdx.x * 256 + threadIdx.x;
    int bh = gid >> 10, de4 = gid & 1023;
    const float4* p = (const float4*)(g_part + (size_t)bh * NG1 * 4096) + de4;
    float4 s = make_float4(0.f, 0.f, 0.f, 0.f);
#pragma unroll
    for (int q = 0; q < NG1; ++q) {
        float4 v = p[(size_t)q * 1024];
        s.x += v.x; s.y += v.y; s.z += v.z; s.w += v.w;
    }
    ((float4*)g_dots)[gid] = s;
}
// ============ k3a: fold dots into Wq ============
__global__ __launch_bounds__(256) void k3_wqe(const float* __restrict__ Wq) {
    const int c0 = blockIdx.x * 64, h = blockIdx.y, b = blockIdx.z;
    const int bh = b * H + h, tid = threadIdx.x;
    __shared__ float sd[4096];
    for (int i = tid; i < 4096; i += 256) sd[i] = g_dots[bh * 4096 + i];
    __syncthreads();
    const int c = c0 + (tid & 63), e0 = (tid >> 6) * 16;
    float acc[16];
#pragma unroll
    for (int e = 0; e < 16; ++e) acc[e] = 0.f;
    for (int d = 0; d < 64; ++d) {
        float w = Wq[(h * 64 + d) * CIN + c];
        const float* sr = &sd[d * 64 + e0];
#pragma unroll
        for (int e = 0; e < 16; ++e) acc[e] += sr[e] * w;
    }
#pragma unroll
    for (int e = 0; e < 16; ++e)
        g_wqe[((size_t)b * INNER + h * 64 + e0 + e) * CIN + c] = acc[e] * (1.f / (float)N);
}
// ============ k3b: fold Wo ============
__global__ __launch_bounds__(256) void k3_wfin(const float* __restrict__ Wo) {
    const int o0 = blockIdx.x * 32, c0 = blockIdx.y * 32, b = blockIdx.z;
    const int tid = threadIdx.x;
    __shared__ float sO[32 * 36], sQ[32 * 33];
    const int cl = tid & 31, ol = (tid >> 5) * 4;
    float acc[4] = {0, 0, 0, 0};
    for (int e0 = 0; e0 < INNER; e0 += 32) {
        __syncthreads();
        int i = tid >> 5, j = tid & 31;
#pragma unroll
        for (int p = 0; p < 4; ++p) {
            int r = i + p * 8;
            sO[j * 36 + r] = Wo[(o0 + r) * INNER + e0 + j];
            sQ[r * 33 + j] = g_wqe[((size_t)b * INNER + e0 + r) * CIN + c0 + j];
        }
        __syncthreads();
#pragma unroll
        for (int e = 0; e < 32; ++e) {
            float q = sQ[e * 33 + cl];
            float4 w = *(const float4*)&sO[e * 36 + ol];
            acc[0] += w.x * q; acc[1] += w.y * q; acc[2] += w.z * q; acc[3] += w.w * q;
        }
    }
#pragma unroll
    for (int j = 0; j < 4; ++j)
        g_wfin[((size_t)b * COUT + o0 + ol + j) * CIN + c0 + cl] = acc[j];
}
// ============ k3w: Wfinal -> fp16 ============
__global__ __launch_bounds__(256) void k3w() {
    size_t i0 = (size_t)blockIdx.x * 256 + threadIdx.x;
    for (size_t i = i0; i < 65536; i += 16384) {
        float4 f = ((const float4*)g_wfin)[i];
        uint2 v;
        v.x = packh2(f.x, f.y);
        v.y = packh2(f.z, f.w);
        *(uint2*)(g_wf16 + i * 4) = v;
    }
}
// ============ K4: streamed-W wmma output GEMM + bias (4 tiles, fully aliased smem) ============
__global__ __launch_bounds__(256) void k4w(const float* __restrict__ bo,
                                           float* __restrict__ out) {
    const int g = blockIdx.x, b = blockIdx.z;
    const int o0 = blockIdx.y * 128;
    const int tid = threadIdx.x, wid = tid >> 5;
    const int wr = wid >> 1, wc = wid & 1;

    extern __shared__ __align__(16) char sm[];
    __half* sA = (__half*)sm;                    // [64][72]
    __half* sW = (__half*)(sm + K1_W);           // [128][72]
    float*  sC = (float*)sm;                     // [64][132] aliases both

    const __half* wsrc = g_wf16 + (size_t)b * COUT * CIN + (size_t)o0 * CIN;

    for (int t = 0; t < TG4; ++t) {
        const int row0 = (g * TG4 + t) * 64;
        const __half* abase = g_ah + ((size_t)(b * N + row0)) * KEXT;

        wmma::fragment<wmma::accumulator, 16, 16, 16, float> c[4];
#pragma unroll
        for (int f = 0; f < 4; ++f) wmma::fill_fragment(c[f], 0.0f);

        for (int kt = 0; kt < KEXT; kt += 64) {
            int ktw = kt & (CIN - 1);
            __syncthreads();
#pragma unroll
            for (int l = 0; l < 2; ++l) {
                int idx = tid + l * 256;
                int r = idx >> 3, c8 = (idx & 7) * 8;
                *(uint4*)(sA + r * LDH + c8) = *(const uint4*)(abase + (size_t)r * KEXT + kt + c8);
            }
#pragma unroll
            for (int l = 0; l < 4; ++l) {
                int idx = tid + l * 256;
                int r = idx >> 3, c8 = (idx & 7) * 8;
                *(uint4*)(sW + r * LDH + c8) = *(const uint4*)(wsrc + (size_t)r * CIN + ktw + c8);
            }
            __syncthreads();
#pragma unroll
            for (int ks = 0; ks < 4; ++ks) {
                wmma::fragment<wmma::matrix_a, 16, 16, 16, __half, wmma::row_major> a;
                wmma::load_matrix_sync(a, sA + (wr * 16) * LDH + ks * 16, LDH);
#pragma unroll
                for (int cf = 0; cf < 4; ++cf) {
                    wmma::fragment<wmma::matrix_b, 16, 16, 16, __half, wmma::col_major> bf;
                    wmma::load_matrix_sync(bf, sW + (wc * 64 + cf * 16) * LDH + ks * 16, LDH);
                    wmma::mma_sync(c[cf], a, bf, c[cf]);
                }
            }
        }
        __syncthreads();
#pragma unroll
        for (int cf = 0; cf < 4; ++cf)
            wmma::store_matrix_sync(sC + (wr * 16) * LDC + wc * 64 + cf * 16, c[cf],
                                    LDC, wmma::mem_row_major);
        __syncthreads();

        for (int idx = tid; idx < 2048; idx += 256) {
            int r = idx >> 5, c4 = (idx & 31) * 4;
            float4 v = *(const float4*)&sC[r * LDC + c4];
            float4 bb = *(const float4*)&bo[o0 + c4];
            v.x += bb.x; v.y += bb.y; v.z += bb.z; v.w += bb.w;
            *(float4*)(out + ((size_t)(b * N + row0 + r)) * COUT + o0 + c4) = v;
        }
        // next tile's first barrier protects sC before sA overwrite
    }
}
// ============ launch ============
extern "C" void kernel_launch(void* const* d_in, const int* in_sizes, int n_in,
                              void* d_out, int out_size)
{
    const float* ux = (const float*)d_in[0];
    const float* Wq = (const float*)d_in[2];
    const float* Wk = (const float*)d_in[3];
    const float* Wv = (const float*)d_in[4];
    const float* Wo = (const float*)d_in[5];
    const float* bo = (const float*)d_in[6];
    float* out = (float*)d_out;

    cudaFuncSetAttribute(k1w, cudaFuncAttributeMaxDynamicSharedMemorySize, SMEM_K1);
    cudaFuncSetAttribute(k4w, cudaFuncAttributeMaxDynamicSharedMemorySize, SMEM_K4);

    k0a<<<256, 256>>>(ux);
    k0w<<<8, 256>>>(Wk, Wv);
    k1w<<<dim3(NG1, H, B), 256, SMEM_K1>>>();
    k2_reduce<<<128, 256>>>();
    k3_wqe<<<dim3(4, H, B), 256>>>(Wq);
    k3_wfin<<<dim3(8, 8, B), 256>>>(Wo);
    k3w<<<64, 256>>>();
    k4w<<<dim3(32, 2, B), 256, SMEM_K4>>>(bo, out);
}

// round 16
// speedup vs baseline: 1.0793x; 1.0793x over previous
#include <cuda_runtime.h>
#include <cuda_fp16.h>
#include <mma.h>
#include <cstdint>
using namespace nvcuda;

// Problem constants
#define B     4
#define N     8192
#define CIN   256
#define H     8
#define D     64
#define INNER 512
#define COUT  256
#define BH    (B*H)
#define KEXT  512          // hi(256) | lo(256)
#define LDH   72           // smem fp16 ld (conflict-free LDSM)
#define LDC   132          // smem fp32 C ld
#define TG1   8            // row-tiles per k1w block
#define TG4   4            // row-tiles per k4w block
#define NG1   16           // k1w tile-groups

// k1w smem layout (bytes): sA/kHI [0,9216) ; sW/kLO+vH [9216,27648) ; sC [27648,61440) ; stat [61440,62464)
#define K1_W    9216
#define K1_KLO  9216
#define K1_VH   18432
#define K1_C    27648
#define K1_STAT 61440
#define SMEM_K1 62464
// k4w: sA [0,9216) ; sW [9216,27648) ; sC aliases [0,33792)
#define SMEM_K4 33792

// ---- device scratch ----
__device__ __align__(16) __half g_ah[(size_t)B * N * KEXT];      // 32 MB A ext (hi|lo)
__device__ __align__(16) __half g_wkv16[H * 128 * CIN];          // per-head [Wk|Wv] fp16
__device__ __align__(16) __half g_wf16[B * COUT * CIN];          // folded weight fp16
__device__ float g_part[(size_t)BH * NG1 * D * D];               // 8 MB dots partials
__device__ float g_dots[BH * D * D];
__device__ float g_wqe[B * INNER * CIN];
__device__ float g_wfin[B * COUT * CIN];

__device__ __forceinline__ uint32_t packh2(float a, float b) {
    __half2 h = __floats2half2_rn(a, b);
    return *reinterpret_cast<uint32_t*>(&h);
}

// ============ k0a: build A ext (hi/lo fp16) ============
__global__ __launch_bounds__(256) void k0a(const float* __restrict__ ux) {
    size_t i0 = (size_t)blockIdx.x * 256 + threadIdx.x;
    const float4* src = (const float4*)ux;
    for (size_t i = i0; i < (size_t)B * N * 64; i += 65536) {
        size_t row = i >> 6;
        int c4 = (int)(i & 63);
        float4 f = src[i];
        __half h0 = __float2half_rn(f.x), h1 = __float2half_rn(f.y);
        __half h2 = __float2half_rn(f.z), h3 = __float2half_rn(f.w);
        uint2 hi, lo;
        hi.x = (uint32_t)__half_as_ushort(h0) | ((uint32_t)__half_as_ushort(h1) << 16);
        hi.y = (uint32_t)__half_as_ushort(h2) | ((uint32_t)__half_as_ushort(h3) << 16);
        lo.x = packh2(f.x - __half2float(h0), f.y - __half2float(h1));
        lo.y = packh2(f.z - __half2float(h2), f.w - __half2float(h3));
        __half* dst = g_ah + row * KEXT + c4 * 4;
        *(uint2*)dst = hi;
        *(uint2*)(dst + CIN) = lo;
    }
}
// ============ k0w: [Wk|Wv] head images fp16 ============
__global__ __launch_bounds__(256) void k0w(const float* __restrict__ Wk,
                                           const float* __restrict__ Wv) {
    int h = blockIdx.x, tid = threadIdx.x;
    for (int i = tid; i < 8192; i += 256) {
        int r = i >> 6, c = (i & 63) * 4;
        const float* src = (r < 64) ? (Wk + ((size_t)(h * 64 + r)) * CIN + c)
                                    : (Wv + ((size_t)(h * 64 + r - 64)) * CIN + c);
        float4 f = *(const float4*)src;
        uint2 v;
        v.x = packh2(f.x, f.y);
        v.y = packh2(f.z, f.w);
        *(uint2*)(g_wkv16 + (size_t)h * 32768 + r * CIN + c) = v;
    }
}
// ============ K1: wmma proj + shfl norm + wmma dots  (minBlocks=2 -> 128 regs, NO SPILLS) ============
__global__ __launch_bounds__(256, 2) void k1w() {
    const int g = blockIdx.x, h = blockIdx.y, b = blockIdx.z;
    const int bh = b * H + h;
    const int tid = threadIdx.x, wid = tid >> 5;
    const int wr = wid >> 1, wc = wid & 1;

    extern __shared__ __align__(16) char sm[];
    __half* sA  = (__half*)sm;                   // [64][72]  (mainloop)
    __half* sW  = (__half*)(sm + K1_W);          // [128][72] (mainloop)
    __half* kHI = (__half*)sm;                   // [64][72]  (epilogue, aliases sA)
    __half* kLO = (__half*)(sm + K1_KLO);        // [64][72]  (aliases sW lo half)
    __half* vH  = (__half*)(sm + K1_VH);         // [64][72]
    float*  sC  = (float*)(sm + K1_C);           // [64][132]
    float*  sStat = (float*)(sm + K1_STAT);      // mean[128] rstd[128]

    // dots accumulators live across all 8 tiles
    wmma::fragment<wmma::accumulator, 16, 16, 16, float> dc0, dc1;
    wmma::fill_fragment(dc0, 0.0f);
    wmma::fill_fragment(dc1, 0.0f);
    const int d0 = (wid >> 1) * 16, e0 = (wid & 1) * 32;

    const __half* wsrc = g_wkv16 + (size_t)h * 32768;

    for (int t = 0; t < TG1; ++t) {
        const int row0 = (g * TG1 + t) * 64;
        const __half* abase = g_ah + ((size_t)(b * N + row0)) * KEXT;

        wmma::fragment<wmma::accumulator, 16, 16, 16, float> c[4];
#pragma unroll
        for (int f = 0; f < 4; ++f) wmma::fill_fragment(c[f], 0.0f);

        for (int kt = 0; kt < KEXT; kt += 64) {
            int ktw = kt & (CIN - 1);
            __syncthreads();
#pragma unroll
            for (int l = 0; l < 2; ++l) {            // A 64x64
                int idx = tid + l * 256;
                int r = idx >> 3, c8 = (idx & 7) * 8;
                *(uint4*)(sA + r * LDH + c8) = *(const uint4*)(abase + (size_t)r * KEXT + kt + c8);
            }
#pragma unroll
            for (int l = 0; l < 4; ++l) {            // W 128x64
                int idx = tid + l * 256;
                int r = idx >> 3, c8 = (idx & 7) * 8;
                *(uint4*)(sW + r * LDH + c8) = *(const uint4*)(wsrc + (size_t)r * CIN + ktw + c8);
            }
            __syncthreads();
#pragma unroll
            for (int ks = 0; ks < 4; ++ks) {
                wmma::fragment<wmma::matrix_a, 16, 16, 16, __half, wmma::row_major> a;
                wmma::load_matrix_sync(a, sA + (wr * 16) * LDH + ks * 16, LDH);
#pragma unroll
                for (int cf = 0; cf < 4; ++cf) {
                    wmma::fragment<wmma::matrix_b, 16, 16, 16, __half, wmma::col_major> bf;
                    wmma::load_matrix_sync(bf, sW + (wc * 64 + cf * 16) * LDH + ks * 16, LDH);
                    wmma::mma_sync(c[cf], a, bf, c[cf]);
                }
            }
        }
        __syncthreads();
#pragma unroll
        for (int cf = 0; cf < 4; ++cf)
            wmma::store_matrix_sync(sC + (wr * 16) * LDC + wc * 64 + cf * 16, c[cf],
                                    LDC, wmma::mem_row_major);
        __syncthreads();

        // stats: 2 threads per (row,grp), shfl-combine
        {
            int p = tid >> 1, h2 = tid & 1;
            int row = p & 63, grp = p >> 6;
            const float* pr = sC + row * LDC + grp * 64 + h2 * 32;
            float s = 0.f, s2 = 0.f;
#pragma unroll
            for (int i = 0; i < 32; ++i) { float x = pr[i]; s += x; s2 += x * x; }
            s  += __shfl_xor_sync(0xFFFFFFFF, s, 1);
            s2 += __shfl_xor_sync(0xFFFFFFFF, s2, 1);
            if (h2 == 0) {
                float mean = s * (1.f / 64.f);
                float var = s2 * (1.f / 64.f) - mean * mean;
                sStat[grp * 64 + row] = mean;
                sStat[128 + grp * 64 + row] = rsqrtf(var + 1e-5f);
            }
        }
        __syncthreads();

        // normalize -> fp16 operands (natural [n][.] layout; k gets hi/lo split)
        {
            int part = tid >> 6, n = tid & 63;
            if (part < 2) {
                float m = sStat[n], rs = sStat[128 + n];
                int c0 = part * 32;
                const float* src = sC + n * LDC + c0;
#pragma unroll
                for (int j = 0; j < 16; ++j) {
                    float x0 = (src[2 * j] - m) * rs;
                    float x1 = (src[2 * j + 1] - m) * rs;
                    __half h0 = __float2half_rn(x0), h1 = __float2half_rn(x1);
                    uint32_t hi = (uint32_t)__half_as_ushort(h0) | ((uint32_t)__half_as_ushort(h1) << 16);
                    uint32_t lo = packh2(x0 - __half2float(h0), x1 - __half2float(h1));
                    *(uint32_t*)(kHI + n * LDH + c0 + 2 * j) = hi;
                    *(uint32_t*)(kLO + n * LDH + c0 + 2 * j) = lo;
                }
            } else {
                float m = sStat[64 + n], rs = sStat[192 + n];
                int c0 = (part - 2) * 32;
                const float* src = sC + n * LDC + 64 + c0;
#pragma unroll
                for (int j = 0; j < 16; ++j) {
                    float x0 = (src[2 * j] - m) * rs;
                    float x1 = (src[2 * j + 1] - m) * rs;
                    *(uint32_t*)(vH + n * LDH + c0 + 2 * j) = packh2(x0, x1);
                }
            }
        }
        __syncthreads();

        // dots via wmma: dots[d,e] += sum_n khat[n,d]*vhat[n,e]
#pragma unroll
        for (int ns = 0; ns < 4; ++ns) {
            wmma::fragment<wmma::matrix_b, 16, 16, 16, __half, wmma::row_major> b0, b1;
            wmma::load_matrix_sync(b0, vH + ns * 16 * LDH + e0, LDH);
            wmma::load_matrix_sync(b1, vH + ns * 16 * LDH + e0 + 16, LDH);
            wmma::fragment<wmma::matrix_a, 16, 16, 16, __half, wmma::col_major> ah, al;
            wmma::load_matrix_sync(ah, kHI + d0 + ns * 16 * LDH, LDH);
            wmma::mma_sync(dc0, ah, b0, dc0);
            wmma::mma_sync(dc1, ah, b1, dc1);
            wmma::load_matrix_sync(al, kLO + d0 + ns * 16 * LDH, LDH);
            wmma::mma_sync(dc0, al, b0, dc0);
            wmma::mma_sync(dc1, al, b1, dc1);
        }
        // next tile's first barrier protects kHI/kLO/vH (alias sA/sW) and sC
    }

    float* pp = g_part + ((size_t)(bh * NG1 + g)) * 4096;
    wmma::store_matrix_sync(pp + d0 * 64 + e0, dc0, 64, wmma::mem_row_major);
    wmma::store_matrix_sync(pp + d0 * 64 + e0 + 16, dc1, 64, wmma::mem_row_major);
}
// ============ k2: reduce 16 partials ============
__global__ __launch_bounds__(256) void k2_reduce() {
    int gid = blockIdx.x * 256 + threadIdx.x;
    int bh = gid >> 10, de4 = gid & 1023;
    const float4* p = (const float4*)(g_part + (size_t)bh * NG1 * 4096) + de4;
    float4 s = make_float4(0.f, 0.f, 0.f, 0.f);
#pragma unroll
    for (int q = 0; q < NG1; ++q) {
        float4 v = p[(size_t)q * 1024];
        s.x += v.x; s.y += v.y; s.z += v.z; s.w += v.w;
    }
    ((float4*)g_dots)[gid] = s;
}
// ============ k3a: fold dots into Wq ============
__global__ __launch_bounds__(256) void k3_wqe(const float* __restrict__ Wq) {
    const int c0 = blockIdx.x * 64, h = blockIdx.y, b = blockIdx.z;
    const int bh = b * H + h, tid = threadIdx.x;
    __shared__ float sd[4096];
    for (int i = tid; i < 4096; i += 256) sd[i] = g_dots[bh * 4096 + i];
    __syncthreads();
    const int c = c0 + (tid & 63), e0 = (tid >> 6) * 16;
    float acc[16];
#pragma unroll
    for (int e = 0; e < 16; ++e) acc[e] = 0.f;
    for (int d = 0; d < 64; ++d) {
        float w = Wq[(h * 64 + d) * CIN + c];
        const float* sr = &sd[d * 64 + e0];
#pragma unroll
        for (int e = 0; e < 16; ++e) acc[e] += sr[e] * w;
    }
#pragma unroll
    for (int e = 0; e < 16; ++e)
        g_wqe[((size_t)b * INNER + h * 64 + e0 + e) * CIN + c] = acc[e] * (1.f / (float)N);
}
// ============ k3b: fold Wo ============
__global__ __launch_bounds__(256) void k3_wfin(const float* __restrict__ Wo) {
    const int o0 = blockIdx.x * 32, c0 = blockIdx.y * 32, b = blockIdx.z;
    const int tid = threadIdx.x;
    __shared__ float sO[32 * 36], sQ[32 * 33];
    const int cl = tid & 31, ol = (tid >> 5) * 4;
    float acc[4] = {0, 0, 0, 0};
    for (int e0 = 0; e0 < INNER; e0 += 32) {
        __syncthreads();
        int i = tid >> 5, j = tid & 31;
#pragma unroll
        for (int p = 0; p < 4; ++p) {
            int r = i + p * 8;
            sO[j * 36 + r] = Wo[(o0 + r) * INNER + e0 + j];
            sQ[r * 33 + j] = g_wqe[((size_t)b * INNER + e0 + r) * CIN + c0 + j];
        }
        __syncthreads();
#pragma unroll
        for (int e = 0; e < 32; ++e) {
            float q = sQ[e * 33 + cl];
            float4 w = *(const float4*)&sO[e * 36 + ol];
            acc[0] += w.x * q; acc[1] += w.y * q; acc[2] += w.z * q; acc[3] += w.w * q;
        }
    }
#pragma unroll
    for (int j = 0; j < 4; ++j)
        g_wfin[((size_t)b * COUT + o0 + ol + j) * CIN + c0 + cl] = acc[j];
}
// ============ k3w: Wfinal -> fp16 ============
__global__ __launch_bounds__(256) void k3w() {
    size_t i0 = (size_t)blockIdx.x * 256 + threadIdx.x;
    for (size_t i = i0; i < 65536; i += 16384) {
        float4 f = ((const float4*)g_wfin)[i];
        uint2 v;
        v.x = packh2(f.x, f.y);
        v.y = packh2(f.z, f.w);
        *(uint2*)(g_wf16 + i * 4) = v;
    }
}
// ============ K4: streamed-W wmma output GEMM + bias (4 tiles, fully aliased smem) ============
__global__ __launch_bounds__(256) void k4w(const float* __restrict__ bo,
                                           float* __restrict__ out) {
    const int g = blockIdx.x, b = blockIdx.z;
    const int o0 = blockIdx.y * 128;
    const int tid = threadIdx.x, wid = tid >> 5;
    const int wr = wid >> 1, wc = wid & 1;

    extern __shared__ __align__(16) char sm[];
    __half* sA = (__half*)sm;                    // [64][72]
    __half* sW = (__half*)(sm + K1_W);           // [128][72]
    float*  sC = (float*)sm;                     // [64][132] aliases both

    const __half* wsrc = g_wf16 + (size_t)b * COUT * CIN + (size_t)o0 * CIN;

    for (int t = 0; t < TG4; ++t) {
        const int row0 = (g * TG4 + t) * 64;
        const __half* abase = g_ah + ((size_t)(b * N + row0)) * KEXT;

        wmma::fragment<wmma::accumulator, 16, 16, 16, float> c[4];
#pragma unroll
        for (int f = 0; f < 4; ++f) wmma::fill_fragment(c[f], 0.0f);

        for (int kt = 0; kt < KEXT; kt += 64) {
            int ktw = kt & (CIN - 1);
            __syncthreads();
#pragma unroll
            for (int l = 0; l < 2; ++l) {
                int idx = tid + l * 256;
                int r = idx >> 3, c8 = (idx & 7) * 8;
                *(uint4*)(sA + r * LDH + c8) = *(const uint4*)(abase + (size_t)r * KEXT + kt + c8);
            }
#pragma unroll
            for (int l = 0; l < 4; ++l) {
                int idx = tid + l * 256;
                int r = idx >> 3, c8 = (idx & 7) * 8;
                *(uint4*)(sW + r * LDH + c8) = *(const uint4*)(wsrc + (size_t)r * CIN + ktw + c8);
            }
            __syncthreads();
#pragma unroll
            for (int ks = 0; ks < 4; ++ks) {
                wmma::fragment<wmma::matrix_a, 16, 16, 16, __half, wmma::row_major> a;
                wmma::load_matrix_sync(a, sA + (wr * 16) * LDH + ks * 16, LDH);
#pragma unroll
                for (int cf = 0; cf < 4; ++cf) {
                    wmma::fragment<wmma::matrix_b, 16, 16, 16, __half, wmma::col_major> bf;
                    wmma::load_matrix_sync(bf, sW + (wc * 64 + cf * 16) * LDH + ks * 16, LDH);
                    wmma::mma_sync(c[cf], a, bf, c[cf]);
                }
            }
        }
        __syncthreads();
#pragma unroll
        for (int cf = 0; cf < 4; ++cf)
            wmma::store_matrix_sync(sC + (wr * 16) * LDC + wc * 64 + cf * 16, c[cf],
                                    LDC, wmma::mem_row_major);
        __syncthreads();

        for (int idx = tid; idx < 2048; idx += 256) {
            int r = idx >> 5, c4 = (idx & 31) * 4;
            float4 v = *(const float4*)&sC[r * LDC + c4];
            float4 bb = *(const float4*)&bo[o0 + c4];
            v.x += bb.x; v.y += bb.y; v.z += bb.z; v.w += bb.w;
            *(float4*)(out + ((size_t)(b * N + row0 + r)) * COUT + o0 + c4) = v;
        }
        // next tile's first barrier protects sC before sA overwrite
    }
}
// ============ launch ============
extern "C" void kernel_launch(void* const* d_in, const int* in_sizes, int n_in,
                              void* d_out, int out_size)
{
    const float* ux = (const float*)d_in[0];
    const float* Wq = (const float*)d_in[2];
    const float* Wk = (const float*)d_in[3];
    const float* Wv = (const float*)d_in[4];
    const float* Wo = (const float*)d_in[5];
    const float* bo = (const float*)d_in[6];
    float* out = (float*)d_out;

    cudaFuncSetAttribute(k1w, cudaFuncAttributeMaxDynamicSharedMemorySize, SMEM_K1);
    cudaFuncSetAttribute(k4w, cudaFuncAttributeMaxDynamicSharedMemorySize, SMEM_K4);

    k0a<<<256, 256>>>(ux);
    k0w<<<8, 256>>>(Wk, Wv);
    k1w<<<dim3(NG1, H, B), 256, SMEM_K1>>>();
    k2_reduce<<<128, 256>>>();
    k3_wqe<<<dim3(4, H, B), 256>>>(Wq);
    k3_wfin<<<dim3(8, 8, B), 256>>>(Wo);
    k3w<<<64, 256>>>();
    k4w<<<dim3(32, 2, B), 256, SMEM_K4>>>(bo, out);
}

// round 17
// speedup vs baseline: 1.3995x; 1.2966x over previous
#include <cuda_runtime.h>
#include <cuda_fp16.h>
#include <mma.h>
#include <cstdint>
using namespace nvcuda;

// Problem constants
#define B     4
#define N     8192
#define CIN   256
#define H     8
#define D     64
#define INNER 512
#define COUT  256
#define BH    (B*H)
#define KEXT  512          // hi(256) | lo(256)
#define LDH   72           // smem fp16 ld (conflict-free LDSM; 144B row, 16B-aligned)
#define LDC   132          // smem fp32 C ld
#define TG1   8            // row-tiles per k1w block
#define TG4   4            // row-tiles per k4w block
#define NG1   16           // k1w tile-groups

// staging: one stage = A(128xLDH fp16 = 18432B) + W(128xLDH fp16 = 18432B)
#define ST_A    0
#define ST_W    18432
#define STAGE   36864
// k1w smem map: stage0 [0,36864) stage1 [36864,73728) sC [73728,107520) stat [107520,108544)
#define K1_C    73728
#define K1_STAT 107520
#define SMEM_K1 108544
// k1w epilogue operand aliases (inside dead stage0): kHI@0, kLO@9216, vH@18432
#define K1_KLO  9216
#define K1_VH   18432
// k4w smem: 2 stages; sC aliases stage0
#define SMEM_K4 73728

// ---- device scratch ----
__device__ __align__(16) __half g_ah[(size_t)B * N * KEXT];      // 32 MB A ext (hi|lo)
__device__ __align__(16) __half g_wkv16[H * 128 * CIN];          // per-head [Wk|Wv] fp16
__device__ __align__(16) __half g_wf16[B * COUT * CIN];          // folded weight fp16
__device__ float g_part[(size_t)BH * NG1 * D * D];               // 8 MB dots partials
__device__ float g_dots[BH * D * D];
__device__ float g_wqe[B * INNER * CIN];
__device__ float g_wfin[B * COUT * CIN];

__device__ __forceinline__ uint32_t packh2(float a, float b) {
    __half2 h = __floats2half2_rn(a, b);
    return *reinterpret_cast<uint32_t*>(&h);
}
__device__ __forceinline__ void cp16(uint32_t sdst, const void* gsrc) {
    asm volatile("cp.async.cg.shared.global [%0], [%1], 16;" :: "r"(sdst), "l"(gsrc));
}
#define CP_COMMIT() asm volatile("cp.async.commit_group;" ::: "memory")
#define CP_WAIT(n)  asm volatile("cp.async.wait_group %0;" :: "n"(n) : "memory")

// ============ k0a: build A ext (hi/lo fp16) ============
__global__ __launch_bounds__(256) void k0a(const float* __restrict__ ux) {
    size_t i0 = (size_t)blockIdx.x * 256 + threadIdx.x;
    const float4* src = (const float4*)ux;
    for (size_t i = i0; i < (size_t)B * N * 64; i += 65536) {
        size_t row = i >> 6;
        int c4 = (int)(i & 63);
        float4 f = src[i];
        __half h0 = __float2half_rn(f.x), h1 = __float2half_rn(f.y);
        __half h2 = __float2half_rn(f.z), h3 = __float2half_rn(f.w);
        uint2 hi, lo;
        hi.x = (uint32_t)__half_as_ushort(h0) | ((uint32_t)__half_as_ushort(h1) << 16);
        hi.y = (uint32_t)__half_as_ushort(h2) | ((uint32_t)__half_as_ushort(h3) << 16);
        lo.x = packh2(f.x - __half2float(h0), f.y - __half2float(h1));
        lo.y = packh2(f.z - __half2float(h2), f.w - __half2float(h3));
        __half* dst = g_ah + row * KEXT + c4 * 4;
        *(uint2*)dst = hi;
        *(uint2*)(dst + CIN) = lo;
    }
}
// ============ k0w: [Wk|Wv] head images fp16 ============
__global__ __launch_bounds__(256) void k0w(const float* __restrict__ Wk,
                                           const float* __restrict__ Wv) {
    int h = blockIdx.x, tid = threadIdx.x;
    for (int i = tid; i < 8192; i += 256) {
        int r = i >> 6, c = (i & 63) * 4;
        const float* src = (r < 64) ? (Wk + ((size_t)(h * 64 + r)) * CIN + c)
                                    : (Wv + ((size_t)(h * 64 + r - 64)) * CIN + c);
        float4 f = *(const float4*)src;
        uint2 v;
        v.x = packh2(f.x, f.y);
        v.y = packh2(f.z, f.w);
        *(uint2*)(g_wkv16 + (size_t)h * 32768 + r * CIN + c) = v;
    }
}
// ============ K1: cp.async 2-stage, M=128 hi|lo fold, wmma proj + norm + wmma dots ============
__global__ __launch_bounds__(256, 2) void k1w() {
    const int g = blockIdx.x, h = blockIdx.y, b = blockIdx.z;
    const int bh = b * H + h;
    const int tid = threadIdx.x, wid = tid >> 5;
    const int wr = wid >> 1, wc = wid & 1;

    extern __shared__ __align__(16) char sm[];
    const uint32_t smb = (uint32_t)__cvta_generic_to_shared(sm);
    float* sC = (float*)(sm + K1_C);
    float* sStat = (float*)(sm + K1_STAT);
    __half* kHI = (__half*)sm;
    __half* kLO = (__half*)(sm + K1_KLO);
    __half* vH  = (__half*)(sm + K1_VH);

    wmma::fragment<wmma::accumulator, 16, 16, 16, float> dc0, dc1;
    wmma::fill_fragment(dc0, 0.0f);
    wmma::fill_fragment(dc1, 0.0f);
    const int d0 = (wid >> 1) * 16, e0 = (wid & 1) * 32;

    const __half* wsrc = g_wkv16 + (size_t)h * 32768;

    for (int t = 0; t < TG1; ++t) {
        const int row0 = (g * TG1 + t) * 64;
        const __half* abase = g_ah + ((size_t)(b * N + row0)) * KEXT;

        // prefetch issuer: A rows 0-63 = hi, 64-127 = lo of same logical rows
        auto prefetch = [&](int ks, int buf) {
            uint32_t sb = smb + buf * STAGE;
            int ktw = ks * 64;
#pragma unroll
            for (int l = 0; l < 4; ++l) {
                int idx = tid + l * 256;
                int r = idx >> 3, c8 = (idx & 7) * 8;
                cp16(sb + ST_A + (r * LDH + c8) * 2,
                     abase + (size_t)(r & 63) * KEXT + (r >> 6) * 256 + ktw + c8);
                cp16(sb + ST_W + (r * LDH + c8) * 2,
                     wsrc + (size_t)r * CIN + ktw + c8);
            }
            CP_COMMIT();
        };

        wmma::fragment<wmma::accumulator, 16, 16, 16, float> chi[4], clo[4];
#pragma unroll
        for (int f = 0; f < 4; ++f) { wmma::fill_fragment(chi[f], 0.0f); wmma::fill_fragment(clo[f], 0.0f); }

        prefetch(0, 0);
        for (int ks = 0; ks < 4; ++ks) {
            if (ks < 3) { prefetch(ks + 1, (ks + 1) & 1); CP_WAIT(1); }
            else        { CP_WAIT(0); }
            __syncthreads();
            const __half* sA = (const __half*)(sm + ((ks & 1) * STAGE) + ST_A);
            const __half* sW = (const __half*)(sm + ((ks & 1) * STAGE) + ST_W);
#pragma unroll
            for (int k4 = 0; k4 < 4; ++k4) {
                wmma::fragment<wmma::matrix_a, 16, 16, 16, __half, wmma::row_major> ah_, al_;
                wmma::load_matrix_sync(ah_, sA + (wr * 16) * LDH + k4 * 16, LDH);
                wmma::load_matrix_sync(al_, sA + (64 + wr * 16) * LDH + k4 * 16, LDH);
#pragma unroll
                for (int cf = 0; cf < 4; ++cf) {
                    wmma::fragment<wmma::matrix_b, 16, 16, 16, __half, wmma::col_major> bf;
                    wmma::load_matrix_sync(bf, sW + (wc * 64 + cf * 16) * LDH + k4 * 16, LDH);
                    wmma::mma_sync(chi[cf], ah_, bf, chi[cf]);
                    wmma::mma_sync(clo[cf], al_, bf, clo[cf]);
                }
            }
            __syncthreads();   // all warps done with buf[ks&1] before it is re-filled
        }

        // C = C_hi + C_lo (fragment-wise), store to sC
#pragma unroll
        for (int cf = 0; cf < 4; ++cf) {
#pragma unroll
            for (int e = 0; e < chi[cf].num_elements; ++e) chi[cf].x[e] += clo[cf].x[e];
            wmma::store_matrix_sync(sC + (wr * 16) * LDC + wc * 64 + cf * 16, chi[cf],
                                    LDC, wmma::mem_row_major);
        }
        __syncthreads();

        // stats: 2 threads per (row,grp), shfl-combine
        {
            int p = tid >> 1, h2 = tid & 1;
            int row = p & 63, grp = p >> 6;
            const float* pr = sC + row * LDC + grp * 64 + h2 * 32;
            float s = 0.f, s2 = 0.f;
#pragma unroll
            for (int i = 0; i < 32; ++i) { float x = pr[i]; s += x; s2 += x * x; }
            s  += __shfl_xor_sync(0xFFFFFFFF, s, 1);
            s2 += __shfl_xor_sync(0xFFFFFFFF, s2, 1);
            if (h2 == 0) {
                float mean = s * (1.f / 64.f);
                float var = s2 * (1.f / 64.f) - mean * mean;
                sStat[grp * 64 + row] = mean;
                sStat[128 + grp * 64 + row] = rsqrtf(var + 1e-5f);
            }
        }
        __syncthreads();

        // normalize -> fp16 operands into dead stage0 (k hi/lo split, v plain)
        {
            int part = tid >> 6, n = tid & 63;
            if (part < 2) {
                float m = sStat[n], rs = sStat[128 + n];
                int c0 = part * 32;
                const float* src = sC + n * LDC + c0;
#pragma unroll
                for (int j = 0; j < 16; ++j) {
                    float x0 = (src[2 * j] - m) * rs;
                    float x1 = (src[2 * j + 1] - m) * rs;
                    __half h0 = __float2half_rn(x0), h1 = __float2half_rn(x1);
                    uint32_t hi = (uint32_t)__half_as_ushort(h0) | ((uint32_t)__half_as_ushort(h1) << 16);
                    uint32_t lo = packh2(x0 - __half2float(h0), x1 - __half2float(h1));
                    *(uint32_t*)(kHI + n * LDH + c0 + 2 * j) = hi;
                    *(uint32_t*)(kLO + n * LDH + c0 + 2 * j) = lo;
                }
            } else {
                float m = sStat[64 + n], rs = sStat[192 + n];
                int c0 = (part - 2) * 32;
                const float* src = sC + n * LDC + 64 + c0;
#pragma unroll
                for (int j = 0; j < 16; ++j) {
                    float x0 = (src[2 * j] - m) * rs;
                    float x1 = (src[2 * j + 1] - m) * rs;
                    *(uint32_t*)(vH + n * LDH + c0 + 2 * j) = packh2(x0, x1);
                }
            }
        }
        __syncthreads();

        // dots via wmma: dots[d,e] += sum_n khat[n,d]*vhat[n,e]
#pragma unroll
        for (int ns = 0; ns < 4; ++ns) {
            wmma::fragment<wmma::matrix_b, 16, 16, 16, __half, wmma::row_major> b0, b1;
            wmma::load_matrix_sync(b0, vH + ns * 16 * LDH + e0, LDH);
            wmma::load_matrix_sync(b1, vH + ns * 16 * LDH + e0 + 16, LDH);
            wmma::fragment<wmma::matrix_a, 16, 16, 16, __half, wmma::col_major> ah_, al_;
            wmma::load_matrix_sync(ah_, kHI + d0 + ns * 16 * LDH, LDH);
            wmma::mma_sync(dc0, ah_, b0, dc0);
            wmma::mma_sync(dc1, ah_, b1, dc1);
            wmma::load_matrix_sync(al_, kLO + d0 + ns * 16 * LDH, LDH);
            wmma::mma_sync(dc0, al_, b0, dc0);
            wmma::mma_sync(dc1, al_, b1, dc1);
        }
        __syncthreads();   // protect stage0 aliases before next tile's prefetch
    }

    float* pp = g_part + ((size_t)(bh * NG1 + g)) * 4096;
    wmma::store_matrix_sync(pp + d0 * 64 + e0, dc0, 64, wmma::mem_row_major);
    wmma::store_matrix_sync(pp + d0 * 64 + e0 + 16, dc1, 64, wmma::mem_row_major);
}
// ============ k2: reduce 16 partials ============
__global__ __launch_bounds__(256) void k2_reduce() {
    int gid = blockIdx.x * 256 + threadIdx.x;
    int bh = gid >> 10, de4 = gid & 1023;
    const float4* p = (const float4*)(g_part + (size_t)bh * NG1 * 4096) + de4;
    float4 s = make_float4(0.f, 0.f, 0.f, 0.f);
#pragma unroll
    for (int q = 0; q < NG1; ++q) {
        float4 v = p[(size_t)q * 1024];
        s.x += v.x; s.y += v.y; s.z += v.z; s.w += v.w;
    }
    ((float4*)g_dots)[gid] = s;
}
// ============ k3a: fold dots into Wq ============
__global__ __launch_bounds__(256) void k3_wqe(const float* __restrict__ Wq) {
    const int c0 = blockIdx.x * 64, h = blockIdx.y, b = blockIdx.z;
    const int bh = b * H + h, tid = threadIdx.x;
    __shared__ float sd[4096];
    for (int i = tid; i < 4096; i += 256) sd[i] = g_dots[bh * 4096 + i];
    __syncthreads();
    const int c = c0 + (tid & 63), e0 = (tid >> 6) * 16;
    float acc[16];
#pragma unroll
    for (int e = 0; e < 16; ++e) acc[e] = 0.f;
    for (int d = 0; d < 64; ++d) {
        float w = Wq[(h * 64 + d) * CIN + c];
        const float* sr = &sd[d * 64 + e0];
#pragma unroll
        for (int e = 0; e < 16; ++e) acc[e] += sr[e] * w;
    }
#pragma unroll
    for (int e = 0; e < 16; ++e)
        g_wqe[((size_t)b * INNER + h * 64 + e0 + e) * CIN + c] = acc[e] * (1.f / (float)N);
}
// ============ k3b: fold Wo ============
__global__ __launch_bounds__(256) void k3_wfin(const float* __restrict__ Wo) {
    const int o0 = blockIdx.x * 32, c0 = blockIdx.y * 32, b = blockIdx.z;
    const int tid = threadIdx.x;
    __shared__ float sO[32 * 36], sQ[32 * 33];
    const int cl = tid & 31, ol = (tid >> 5) * 4;
    float acc[4] = {0, 0, 0, 0};
    for (int e0 = 0; e0 < INNER; e0 += 32) {
        __syncthreads();
        int i = tid >> 5, j = tid & 31;
#pragma unroll
        for (int p = 0; p < 4; ++p) {
            int r = i + p * 8;
            sO[j * 36 + r] = Wo[(o0 + r) * INNER + e0 + j];
            sQ[r * 33 + j] = g_wqe[((size_t)b * INNER + e0 + r) * CIN + c0 + j];
        }
        __syncthreads();
#pragma unroll
        for (int e = 0; e < 32; ++e) {
            float q = sQ[e * 33 + cl];
            float4 w = *(const float4*)&sO[e * 36 + ol];
            acc[0] += w.x * q; acc[1] += w.y * q; acc[2] += w.z * q; acc[3] += w.w * q;
        }
    }
#pragma unroll
    for (int j = 0; j < 4; ++j)
        g_wfin[((size_t)b * COUT + o0 + ol + j) * CIN + c0 + cl] = acc[j];
}
// ============ k3w: Wfinal -> fp16 ============
__global__ __launch_bounds__(256) void k3w() {
    size_t i0 = (size_t)blockIdx.x * 256 + threadIdx.x;
    for (size_t i = i0; i < 65536; i += 16384) {
        float4 f = ((const float4*)g_wfin)[i];
        uint2 v;
        v.x = packh2(f.x, f.y);
        v.y = packh2(f.z, f.w);
        *(uint2*)(g_wf16 + i * 4) = v;
    }
}
// ============ K4: cp.async 2-stage, M=128 hi|lo fold, output GEMM + bias ============
__global__ __launch_bounds__(256) void k4w(const float* __restrict__ bo,
                                           float* __restrict__ out) {
    const int g = blockIdx.x, b = blockIdx.z;
    const int o0 = blockIdx.y * 128;
    const int tid = threadIdx.x, wid = tid >> 5;
    const int wr = wid >> 1, wc = wid & 1;

    extern __shared__ __align__(16) char sm[];
    const uint32_t smb = (uint32_t)__cvta_generic_to_shared(sm);
    float* sC = (float*)sm;                     // aliases stage0

    const __half* wsrc = g_wf16 + (size_t)b * COUT * CIN + (size_t)o0 * CIN;

    for (int t = 0; t < TG4; ++t) {
        const int row0 = (g * TG4 + t) * 64;
        const __half* abase = g_ah + ((size_t)(b * N + row0)) * KEXT;

        auto prefetch = [&](int ks, int buf) {
            uint32_t sb = smb + buf * STAGE;
            int ktw = ks * 64;
#pragma unroll
            for (int l = 0; l < 4; ++l) {
                int idx = tid + l * 256;
                int r = idx >> 3, c8 = (idx & 7) * 8;
                cp16(sb + ST_A + (r * LDH + c8) * 2,
                     abase + (size_t)(r & 63) * KEXT + (r >> 6) * 256 + ktw + c8);
                cp16(sb + ST_W + (r * LDH + c8) * 2,
                     wsrc + (size_t)r * CIN + ktw + c8);
            }
            CP_COMMIT();
        };

        wmma::fragment<wmma::accumulator, 16, 16, 16, float> chi[4], clo[4];
#pragma unroll
        for (int f = 0; f < 4; ++f) { wmma::fill_fragment(chi[f], 0.0f); wmma::fill_fragment(clo[f], 0.0f); }

        prefetch(0, 0);
        for (int ks = 0; ks < 4; ++ks) {
            if (ks < 3) { prefetch(ks + 1, (ks + 1) & 1); CP_WAIT(1); }
            else        { CP_WAIT(0); }
            __syncthreads();
            const __half* sA = (const __half*)(sm + ((ks & 1) * STAGE) + ST_A);
            const __half* sW = (const __half*)(sm + ((ks & 1) * STAGE) + ST_W);
#pragma unroll
            for (int k4 = 0; k4 < 4; ++k4) {
                wmma::fragment<wmma::matrix_a, 16, 16, 16, __half, wmma::row_major> ah_, al_;
                wmma::load_matrix_sync(ah_, sA + (wr * 16) * LDH + k4 * 16, LDH);
                wmma::load_matrix_sync(al_, sA + (64 + wr * 16) * LDH + k4 * 16, LDH);
#pragma unroll
                for (int cf = 0; cf < 4; ++cf) {
                    wmma::fragment<wmma::matrix_b, 16, 16, 16, __half, wmma::col_major> bf;
                    wmma::load_matrix_sync(bf, sW + (wc * 64 + cf * 16) * LDH + k4 * 16, LDH);
                    wmma::mma_sync(chi[cf], ah_, bf, chi[cf]);
                    wmma::mma_sync(clo[cf], al_, bf, clo[cf]);
                }
            }
            __syncthreads();
        }

#pragma unroll
        for (int cf = 0; cf < 4; ++cf) {
#pragma unroll
            for (int e = 0; e < chi[cf].num_elements; ++e) chi[cf].x[e] += clo[cf].x[e];
            wmma::store_matrix_sync(sC + (wr * 16) * LDC + wc * 64 + cf * 16, chi[cf],
                                    LDC, wmma::mem_row_major);
        }
        __syncthreads();

        for (int idx = tid; idx < 2048; idx += 256) {
            int r = idx >> 5, c4 = (idx & 31) * 4;
            float4 v = *(const float4*)&sC[r * LDC + c4];
            float4 bb = *(const float4*)&bo[o0 + c4];
            v.x += bb.x; v.y += bb.y; v.z += bb.z; v.w += bb.w;
            *(float4*)(out + ((size_t)(b * N + row0 + r)) * COUT + o0 + c4) = v;
        }
        __syncthreads();   // sC (stage0 alias) reads done before next tile's prefetch
    }
}
// ============ launch ============
extern "C" void kernel_launch(void* const* d_in, const int* in_sizes, int n_in,
                              void* d_out, int out_size)
{
    const float* ux = (const float*)d_in[0];
    const float* Wq = (const float*)d_in[2];
    const float* Wk = (const float*)d_in[3];
    const float* Wv = (const float*)d_in[4];
    const float* Wo = (const float*)d_in[5];
    const float* bo = (const float*)d_in[6];
    float* out = (float*)d_out;

    cudaFuncSetAttribute(k1w, cudaFuncAttributeMaxDynamicSharedMemorySize, SMEM_K1);
    cudaFuncSetAttribute(k4w, cudaFuncAttributeMaxDynamicSharedMemorySize, SMEM_K4);

    k0a<<<256, 256>>>(ux);
    k0w<<<8, 256>>>(Wk, Wv);
    k1w<<<dim3(NG1, H, B), 256, SMEM_K1>>>();
    k2_reduce<<<128, 256>>>();
    k3_wqe<<<dim3(4, H, B), 256>>>(Wq);
    k3_wfin<<<dim3(8, 8, B), 256>>>(Wo);
    k3w<<<64, 256>>>();
    k4w<<<dim3(32, 2, B), 256, SMEM_K4>>>(bo, out);
}